// round 10
// baseline (speedup 1.0000x reference)
#include <cuda_runtime.h>
#include <cstdint>

// ---------------------------------------------------------------------------
// MPS amplitude contraction, segment-table approach (v10).
// amplitude(s) = left[x0] . B[x1] ... B[x62] . right[x63]   (complex, D=16)
//
// Split: Lvec covers x0..x13, 6 x Seg6 cover x14..x49, Rvec covers x50..x63.
// v10: samples sorted by 12-bit key (x14..x25) so warps have uniform
//      stage-1/2 segment indices -> rotated LDS.128 collapses 4 wavefronts
//      to 1 (stage1) / 2 (stage2). Pipeline:
//      kZero -> k0(pack+hist) -> kA(Seg6 build + scan) -> kB(tables+scatter)
//      -> k_main(sorted walk, out scattered by original index).
// ---------------------------------------------------------------------------

typedef unsigned long long ull;

__device__ float2 g_seg [64 * 256];
__device__ float2 g_lv8 [256 * 16];
__device__ float2 g_rv8 [256 * 16];
__device__ float2 g_lvec[16384 * 16];
__device__ float2 g_rvec[16384 * 16];
__device__ ull    g_xpack[131072];
__device__ ull    g_xsort[131072];
__device__ int    g_sidx [131072];
__device__ int    g_hist [4096];
__device__ int    g_binOff[4096];

// ---- packed fp32x2 helpers ----
__device__ __forceinline__ ull pack2(float lo, float hi) {
    ull r; asm("mov.b64 %0, {%1,%2};" : "=l"(r) : "f"(lo), "f"(hi)); return r;
}
__device__ __forceinline__ void unpack2(ull v, float& lo, float& hi) {
    asm("mov.b64 {%0,%1}, %2;" : "=f"(lo), "=f"(hi) : "l"(v));
}
__device__ __forceinline__ ull ffma2(ull a, ull b, ull c) {
    ull d; asm("fma.rn.f32x2 %0, %1, %2, %3;" : "=l"(d) : "l"(a), "l"(b), "l"(c));
    return d;
}
__device__ __forceinline__ void lds128(unsigned addr, ull& p0, ull& p1) {
    asm volatile("ld.shared.v2.b64 {%0,%1}, [%2];" : "=l"(p0), "=l"(p1) : "r"(addr));
}
__device__ __forceinline__ void sts128(unsigned addr, ull p0, ull p1) {
    asm volatile("st.shared.v2.b64 [%0], {%1,%2};" :: "r"(addr), "l"(p0), "l"(p1));
}
__device__ __forceinline__ void ldg128(const void* p, ull& p0, ull& p1) {
    asm volatile("ld.global.nc.v2.b64 {%0,%1}, [%2];" : "=l"(p0), "=l"(p1) : "l"(p));
}

// scalar complex fma: (rr,ri) += (ax+i ay) * (bx+i by)
__device__ __forceinline__ void cfma(float& rr, float& ri, float ax, float ay,
                                     float bx, float by) {
    rr = fmaf(ax, bx, rr);
    rr = fmaf(-ay, by, rr);
    ri = fmaf(ax, by, ri);
    ri = fmaf(ay, bx, ri);
}

// 16x16 complex matmul, one output element per thread (e = i*16+k, 256 thr)
__device__ __forceinline__ void mm16(const float2* A, const float2* Bm,
                                     float2* C, int e) {
    int i = e >> 4, k = e & 15;
    float xr0 = 0.f, xi0 = 0.f, xr1 = 0.f, xi1 = 0.f;
#pragma unroll
    for (int j = 0; j < 16; j += 2) {
        float2 a0 = A[(i << 4) + j],     b0 = Bm[(j << 4) + k];
        float2 a1 = A[(i << 4) + j + 1], b1 = Bm[((j + 1) << 4) + k];
        cfma(xr0, xi0, a0.x, a0.y, b0.x, b0.y);
        cfma(xr1, xi1, a1.x, a1.y, b1.x, b1.y);
    }
    C[e] = make_float2(xr0 + xr1, xi0 + xi1);
}

// ---------------------------------------------------------------------------
// kZero: clear histogram (4096 ints).
// ---------------------------------------------------------------------------
__global__ void kZero() {
    int t = blockIdx.x * blockDim.x + threadIdx.x;
    if (t < 4096) g_hist[t] = 0;
}

// ---------------------------------------------------------------------------
// k0_pack: warp W packs samples [32W, 32W+32); packed bit (63-t) = x_t.
// Also builds the 12-bit (x14..x25) histogram.
// ---------------------------------------------------------------------------
__global__ void k0_pack(const int* __restrict__ x, int N) {
    int W = (blockIdx.x * blockDim.x + threadIdx.x) >> 5;
    int lane = threadIdx.x & 31;
    int s0 = W << 5;
    if (s0 >= N) return;
    ull mine = 0;
#pragma unroll 4
    for (int q = 0; q < 32; q++) {
        size_t base = (size_t)(s0 + q) << 6;
        unsigned b0 = __ballot_sync(0xFFFFFFFFu, x[base + lane] & 1);
        unsigned b1 = __ballot_sync(0xFFFFFFFFu, x[base + 32 + lane] & 1);
        ull packed = ((ull)__brev(b0) << 32) | (ull)__brev(b1);
        if (lane == q) mine = packed;
    }
    g_xpack[s0 + lane] = mine;
    atomicAdd(&g_hist[(unsigned)(mine >> 38) & 0xFFFu], 1);
}

// ---------------------------------------------------------------------------
// kA: 65 blocks x 512 threads.
// Blocks 0..63: build Seg6[c] (parallel Seg3 trees) + Lv8/Rv8 slices.
// Block 64: exclusive scan of g_hist -> g_binOff.
// ---------------------------------------------------------------------------
__global__ __launch_bounds__(512) void kA(
        const float* __restrict__ br_, const float* __restrict__ bi_,
        const float* __restrict__ lr_, const float* __restrict__ li_,
        const float* __restrict__ rr_, const float* __restrict__ ri_) {
    int c = blockIdx.x;
    if (c < 64) {
        __shared__ float2 sB[512], sT[2][256], sP[2][256], sS6[256];
        __shared__ float2 sLv2[64], sRv2[64];
        __shared__ float sLr[32], sLi[32], sRr[32], sRi[32];
        int e = threadIdx.x;
        int half = e >> 8, e2 = e & 255;

        sB[e] = make_float2(br_[e], bi_[e]);
        if (e < 32) { sLr[e] = lr_[e]; sLi[e] = li_[e]; sRr[e] = rr_[e]; sRi[e] = ri_[e]; }
        __syncthreads();

        int a = c >> 3, b = c & 7;
        int v = half ? b : a;
        mm16(sB + (((v >> 1) & 1) << 8), sB + ((v & 1) << 8), sT[half], e2);
        __syncthreads();
        mm16(sB + ((v >> 2) << 8), sT[half], sP[half], e2);
        __syncthreads();
        if (half == 0) mm16(sP[0], sP[1], sS6, e2);   // Seg6[c] = Seg3[a].Seg3[b]
        __syncthreads();

        if (half == 0) g_seg[(c << 8) + e2] = sS6[e2];

        if (e < 64) {  // Lv2[(s<<1)|bb][k]
            int vv = e >> 4, k = e & 15, s = vv >> 1, bb = vv & 1;
            float xr = 0.f, xi = 0.f;
#pragma unroll
            for (int j = 0; j < 16; j++) {
                float2 m = sB[(bb << 8) + (j << 4) + k];
                cfma(xr, xi, sLr[s * 16 + j], sLi[s * 16 + j], m.x, m.y);
            }
            sLv2[e] = make_float2(xr, xi);
        } else if (e < 128) {  // Rv2[(bb<<1)|r][i]
            int t2 = e - 64, vv = t2 >> 4, i = t2 & 15, bb = vv >> 1, r = vv & 1;
            float xr = 0.f, xi = 0.f;
#pragma unroll
            for (int j = 0; j < 16; j++) {
                float2 m = sB[(bb << 8) + (i << 4) + j];
                cfma(xr, xi, m.x, m.y, sRr[r * 16 + j], sRi[r * 16 + j]);
            }
            sRv2[t2] = make_float2(xr, xi);
        }
        __syncthreads();

        if (e < 64) {  // Lv8[(a2<<6)|c][k]
            int a2 = e >> 4, k = e & 15;
            float xr = 0.f, xi = 0.f;
#pragma unroll
            for (int j = 0; j < 16; j++) {
                float2 o = sLv2[(a2 << 4) + j];
                float2 m = sS6[(j << 4) + k];
                cfma(xr, xi, o.x, o.y, m.x, m.y);
            }
            g_lv8[(((a2 << 6) | c) << 4) + k] = make_float2(xr, xi);
        } else if (e < 128) {  // Rv8[(c<<2)|b2][i]
            int t2 = e - 64, b2 = t2 >> 4, i = t2 & 15;
            float xr = 0.f, xi = 0.f;
#pragma unroll
            for (int j = 0; j < 16; j++) {
                float2 m = sS6[(i << 4) + j];
                float2 w = sRv2[(b2 << 4) + j];
                cfma(xr, xi, m.x, m.y, w.x, w.y);
            }
            g_rv8[(((c << 2) | b2) << 4) + i] = make_float2(xr, xi);
        }
    } else {
        // ---- block 64: exclusive scan g_hist[4096] -> g_binOff ----
        __shared__ int sc[512];
        int t = threadIdx.x;
        int v[8]; int s8 = 0;
#pragma unroll
        for (int j = 0; j < 8; j++) { v[j] = g_hist[t * 8 + j]; s8 += v[j]; }
        sc[t] = s8;
        __syncthreads();
        for (int off = 1; off < 512; off <<= 1) {
            int xv = sc[t];
            int yv = (t >= off) ? sc[t - off] : 0;
            __syncthreads();
            sc[t] = xv + yv;
            __syncthreads();
        }
        int run = (t > 0) ? sc[t - 1] : 0;
#pragma unroll
        for (int j = 0; j < 8; j++) { g_binOff[t * 8 + j] = run; run += v[j]; }
    }
}

// ---------------------------------------------------------------------------
// kB: 256 blocks x 256 threads. Table expansion (split p-ranges) + scatter.
// Blocks 0..127:  L side, c = blk>>1, p-half = blk&1.
// Blocks 128..255: R side, c = (blk-128)>>1, p-half = (blk-128)&1.
// All blocks then scatter g_xpack into sorted order via g_binOff cursors.
// ---------------------------------------------------------------------------
__global__ void kB(int N) {
    __shared__ float2 S[256];
    int blk = blockIdx.x;
    int t = threadIdx.x;

    if (blk < 128) {
        int c = blk >> 1, ph = blk & 1;
        S[t] = g_seg[(c << 8) + t];           // S[j*16+k] = Seg6[c][j][k]
        __syncthreads();
        int k = t & 15, a8l = t >> 4;
#pragma unroll 1
        for (int p = ph * 8; p < ph * 8 + 8; p++) {
            int a8 = (p << 4) | a8l;
            const float2* w = g_lv8 + (a8 << 4);
            float xr0 = 0.f, xi0 = 0.f, xr1 = 0.f, xi1 = 0.f;
#pragma unroll
            for (int j = 0; j < 16; j += 2) {
                float2 o0 = __ldg(&w[j]),     b0 = S[(j << 4) + k];
                float2 o1 = __ldg(&w[j + 1]), b1 = S[((j + 1) << 4) + k];
                cfma(xr0, xi0, o0.x, o0.y, b0.x, b0.y);
                cfma(xr1, xi1, o1.x, o1.y, b1.x, b1.y);
            }
            g_lvec[(((a8 << 6) | c) << 4) + k] = make_float2(xr0 + xr1, xi0 + xi1);
        }
    } else {
        int b2 = blk - 128;
        int c = b2 >> 1, ph = b2 & 1;
        {
            int i = t >> 4, j = t & 15;
            S[(j << 4) | i] = g_seg[(c << 8) + t];  // transposed stage
        }
        __syncthreads();
        int il = t & 15, b8l = t >> 4;
#pragma unroll 1
        for (int p = ph * 8; p < ph * 8 + 8; p++) {
            int b8 = (p << 4) | b8l;
            const float2* w = g_rv8 + (b8 << 4);
            float xr0 = 0.f, xi0 = 0.f, xr1 = 0.f, xi1 = 0.f;
#pragma unroll
            for (int j = 0; j < 16; j += 2) {
                float2 w0 = __ldg(&w[j]),     b0 = S[(j << 4) + il];
                float2 w1 = __ldg(&w[j + 1]), b1 = S[((j + 1) << 4) + il];
                cfma(xr0, xi0, b0.x, b0.y, w0.x, w0.y);
                cfma(xr1, xi1, b1.x, b1.y, w1.x, w1.y);
            }
            g_rvec[(((c << 8) | b8) << 4) + il] = make_float2(xr0 + xr1, xi0 + xi1);
        }
    }

    // ---- scatter into sorted order (bin cursors via atomicAdd) ----
    for (int s = blk * 256 + t; s < N; s += 256 * 256) {
        ull packed = g_xpack[s];
        unsigned key = (unsigned)(packed >> 38) & 0xFFFu;
        int pos = atomicAdd(&g_binOff[key], 1);
        g_xsort[pos] = packed;
        g_sidx[pos] = s;
    }
}

// ---------------------------------------------------------------------------
// Main kernel. Walks SORTED samples (warp-uniform stage-1/2 segment idx ->
// rotated LDS.128 becomes broadcast: 1-2 wavefronts instead of 4). Staged
// warp-cooperative Lvec/Rvec gathers; fma.rn.f32x2 dual accumulators.
// Output scattered to original sample positions.
// ---------------------------------------------------------------------------
__global__ __launch_bounds__(512) void k_main(float* __restrict__ out, int N) {
    extern __shared__ float2 smem_all[];
    float2* sSeg = smem_all;                    // 16384 float2 = 128 KB

    {
        const float4* src = reinterpret_cast<const float4*>(g_seg);
        float4* dst = reinterpret_cast<float4*>(sSeg);
        for (int e = threadIdx.x; e < 64 * 128; e += blockDim.x) dst[e] = src[e];
    }
    __syncthreads();

    unsigned sb;
    asm("{ .reg .u64 t; cvta.to.shared.u64 t, %1; cvt.u32.u64 %0, t; }"
        : "=r"(sb) : "l"(smem_all));
    const unsigned stgb   = sb + 131072u;            // staging base (bytes)
    const unsigned lane   = threadIdx.x & 31u;
    const unsigned rot    = threadIdx.x & 7u;
    const unsigned rot16  = rot << 4;
    const unsigned rot256 = rot << 8;
    const unsigned myStg  = stgb + ((unsigned)threadIdx.x << 7);
    const unsigned warpStg = stgb + ((unsigned)(threadIdx.x & ~31u) << 7);
    const int sub    = (int)(lane >> 3);             // 0..3
    const int chunku = (int)(lane & 7);              // 16B chunk this lane moves

    int chunk = (N + gridDim.x - 1) / gridDim.x;
    int start = blockIdx.x * chunk;
    int end = min(start + chunk, N);

    for (int base = start + (int)((threadIdx.x >> 5) << 5); base < end;
         base += (int)blockDim.x) {
        int s = base + (int)lane;
        bool active = s < end;
        ull packed = active ? __ldg(&g_xsort[s]) : 0ull;
        int orig   = active ? __ldg(&g_sidx[s]) : 0;
        unsigned idxl = (unsigned)(packed >> 50);         // x0..x13
        unsigned idxr = (unsigned)packed & 0x3FFFu;       // x50..x63
        ull sp = packed << 14;                            // x14 at bit 63

        // ---- staged Lvec gather (slots swizzled by owner&7) ----
#pragma unroll
        for (int g = 0; g < 8; g++) {
            int owner = (g << 2) + sub;
            unsigned oidx = __shfl_sync(0xFFFFFFFFu, idxl, owner);
            const char* p = (const char*)g_lvec + ((size_t)oidx << 7) + (chunku << 4);
            ull a, b; ldg128(p, a, b);
            unsigned slot = (unsigned)(chunku ^ (owner & 7));
            sts128(warpStg + ((unsigned)owner << 7) + (slot << 4), a, b);
        }
        __syncwarp();

        float mr[16], mi[16];
#pragma unroll
        for (int u = 0; u < 8; u++) {                    // logical order
            unsigned slot = (unsigned)u ^ rot;
            ull a, b; lds128(myStg + (slot << 4), a, b);
            unpack2(a, mr[2 * u],     mi[2 * u]);
            unpack2(b, mr[2 * u + 1], mi[2 * u + 1]);
        }
        __syncwarp();   // all reads done before staging is reused below

        // ---- matvec 1 (sorted: idx warp-uniform -> broadcast wavefronts) ----
        {
            unsigned idx = (unsigned)(sp >> 58);
            sp <<= 6;
            unsigned mb = sb + (idx << 11);
            ull P[16], Q[16];
#pragma unroll
            for (int e = 0; e < 16; e++) { P[e] = 0ull; Q[e] = 0ull; }
            unsigned pu[8];
#pragma unroll
            for (int u = 0; u < 8; u++) pu[u] = mb + ((rot16 + (u << 4)) & 127u);
#pragma unroll
            for (int i = 0; i < 16; i++) {
                float ar = mr[i], ai = mi[i];
                ull arr = pack2(ar, ar), ai2 = pack2(ai, -ai);
#pragma unroll
                for (int u = 0; u < 8; u++) {
                    ull b0, b1;
                    lds128(pu[u] + (unsigned)(i << 7), b0, b1);
                    P[2 * u]     = ffma2(arr, b0, P[2 * u]);
                    Q[2 * u]     = ffma2(ai2, b0, Q[2 * u]);
                    P[2 * u + 1] = ffma2(arr, b1, P[2 * u + 1]);
                    Q[2 * u + 1] = ffma2(ai2, b1, Q[2 * u + 1]);
                }
            }
#pragma unroll
            for (int e = 0; e < 16; e++) {
                float pl, ph, ql, qh;
                unpack2(P[e], pl, ph);
                unpack2(Q[e], ql, qh);
                mr[e] = pl + qh;   // nr = ar*bx - ai*by
                mi[e] = ph + ql;   // ni = ar*by + ai*bx
            }
        }

        // ---- matvecs 2..6: state pair u holds logical pair (u+rot)&7 ----
#pragma unroll 1
        for (int kseg = 1; kseg < 6; kseg++) {
            unsigned idx = (unsigned)(sp >> 58);
            sp <<= 6;
            unsigned mb = sb + (idx << 11);
            ull P[16], Q[16];
#pragma unroll
            for (int e = 0; e < 16; e++) { P[e] = 0ull; Q[e] = 0ull; }
            unsigned pu[8];
#pragma unroll
            for (int u = 0; u < 8; u++) pu[u] = mb + ((rot16 + (u << 4)) & 127u);
#pragma unroll
            for (int spn = 0; spn < 8; spn++) {
                unsigned row = (rot256 + (unsigned)(spn << 8)) & 2047u;
#pragma unroll
                for (int hf = 0; hf < 2; hf++) {
                    float ar = mr[2 * spn + hf], ai = mi[2 * spn + hf];
                    ull arr = pack2(ar, ar), ai2 = pack2(ai, -ai);
#pragma unroll
                    for (int u = 0; u < 8; u++) {
                        ull b0, b1;
                        lds128(pu[u] + row + (unsigned)(hf << 7), b0, b1);
                        P[2 * u]     = ffma2(arr, b0, P[2 * u]);
                        Q[2 * u]     = ffma2(ai2, b0, Q[2 * u]);
                        P[2 * u + 1] = ffma2(arr, b1, P[2 * u + 1]);
                        Q[2 * u + 1] = ffma2(ai2, b1, Q[2 * u + 1]);
                    }
                }
            }
#pragma unroll
            for (int e = 0; e < 16; e++) {
                float pl, ph, ql, qh;
                unpack2(P[e], pl, ph);
                unpack2(Q[e], ql, qh);
                mr[e] = pl + qh;
                mi[e] = ph + ql;
            }
        }

        // ---- staged Rvec gather (unswizzled; read order is rotated) ----
#pragma unroll
        for (int g = 0; g < 8; g++) {
            int owner = (g << 2) + sub;
            unsigned oidx = __shfl_sync(0xFFFFFFFFu, idxr, owner);
            const char* p = (const char*)g_rvec + ((size_t)oidx << 7) + (chunku << 4);
            ull a, b; ldg128(p, a, b);
            sts128(warpStg + ((unsigned)owner << 7) + ((unsigned)chunku << 4), a, b);
        }
        __syncwarp();

        float accr = 0.f, acci = 0.f;
#pragma unroll
        for (int u = 0; u < 8; u++) {
            unsigned lp = (u + rot) & 7u;               // logical pair at step u
            ull a, b; lds128(myStg + (lp << 4), a, b);
            float c0x, c0y, c1x, c1y;
            unpack2(a, c0x, c0y);
            unpack2(b, c1x, c1y);
            int e0 = 2 * u, e1 = 2 * u + 1;
            accr = fmaf(mr[e0], c0x, accr);  accr = fmaf(-mi[e0], c0y, accr);
            acci = fmaf(mr[e0], c0y, acci);  acci = fmaf(mi[e0], c0x, acci);
            accr = fmaf(mr[e1], c1x, accr);  accr = fmaf(-mi[e1], c1y, accr);
            acci = fmaf(mr[e1], c1y, acci);  acci = fmaf(mi[e1], c1x, acci);
        }
        __syncwarp();   // staging reused next iteration

        if (active) {
            out[orig]     = accr;
            out[N + orig] = acci;
        }
    }
}

// ---------------------------------------------------------------------------
// kernel_launch
// inputs (metadata order): x, left_r, left_i, bulk_r, bulk_i, right_r, right_i
// out: float32, [2, N] flattened (re then im)
// ---------------------------------------------------------------------------
extern "C" void kernel_launch(void* const* d_in, const int* in_sizes, int n_in,
                              void* d_out, int out_size) {
    const int*   x       = (const int*)d_in[0];
    const float* left_r  = (const float*)d_in[1];
    const float* left_i  = (const float*)d_in[2];
    const float* bulk_r  = (const float*)d_in[3];
    const float* bulk_i  = (const float*)d_in[4];
    const float* right_r = (const float*)d_in[5];
    const float* right_i = (const float*)d_in[6];
    float* out = (float*)d_out;

    int N = in_sizes[0] / 64;

    static const size_t kSmem = 192 * 1024;  // 128 KB table + 64 KB staging
    cudaFuncSetAttribute(k_main, cudaFuncAttributeMaxDynamicSharedMemorySize,
                         (int)kSmem);

    kZero<<<16, 256>>>();
    k0_pack<<<(131072 + 255) / 256, 256>>>(x, N);
    kA<<<65, 512>>>(bulk_r, bulk_i, left_r, left_i, right_r, right_i);
    kB<<<256, 256>>>(N);
    k_main<<<148, 512, kSmem>>>(out, N);
}